// round 11
// baseline (speedup 1.0000x reference)
#include <cuda_runtime.h>
#include <cstdint>

#define BATCHES 16
#define NPTS    65536
#define NSAMP   2048
#define CPB     8                  // CTAs per cluster (= per batch)
#define TPB     1024
#define PPT     8                  // points per thread
#define SLAB    (NPTS / CPB)       // 8192 points per CTA

__device__ __forceinline__ uint32_t smem_u32(const void* p) {
    return (uint32_t)__cvta_generic_to_shared(p);
}
__device__ __forceinline__ void st_remote_u64(uint32_t laddr, uint32_t rank,
                                              unsigned long long v) {
    uint32_t raddr;
    asm volatile("mapa.shared::cluster.u32 %0, %1, %2;"
                 : "=r"(raddr) : "r"(laddr), "r"(rank));
    asm volatile("st.shared::cluster.u64 [%0], %1;"
                 :: "r"(raddr), "l"(v) : "memory");
}
// release-arrive on CTA `rank`'s mbarrier (orders prior cluster-space stores)
__device__ __forceinline__ void mbar_arrive_remote(uint32_t lmbar, uint32_t rank) {
    asm volatile(
        "{\n\t"
        ".reg .b32 r;\n\t"
        "mapa.shared::cluster.u32 r, %0, %1;\n\t"
        "mbarrier.arrive.release.cluster.shared::cluster.b64 _, [r];\n\t"
        "}"
        :: "r"(lmbar), "r"(rank) : "memory");
}
__device__ __forceinline__ void mbar_wait_parity(uint32_t mbar, uint32_t parity) {
    asm volatile(
        "{\n\t"
        ".reg .pred P;\n\t"
        "WL_%=:\n\t"
        "mbarrier.try_wait.parity.acquire.cluster.shared::cta.b64 P, [%0], %1, 0x989680;\n\t"
        "@P bra.uni WD_%=;\n\t"
        "bra.uni WL_%=;\n\t"
        "WD_%=:\n\t"
        "}"
        :: "r"(mbar), "r"(parity) : "memory");
}
__device__ __forceinline__ void cluster_barrier() {
    asm volatile("barrier.cluster.arrive.aligned;" ::: "memory");
    asm volatile("barrier.cluster.wait.aligned;"   ::: "memory");
}

__global__ void __launch_bounds__(TPB, 1) __cluster_dims__(CPB, 1, 1)
fps_cluster(const float* __restrict__ points, float* __restrict__ out)
{
    const int tid  = threadIdx.x;
    const int warp = tid >> 5;
    const int lane = tid & 31;
    uint32_t rank;
    asm("mov.u32 %0, %%cluster_ctarank;" : "=r"(rank));
    const int batch = blockIdx.x / CPB;
    const float* bp = points + (size_t)batch * NPTS * 3;

    __shared__ unsigned long long warp_keys[TPB / 32];
    __shared__ unsigned long long cta_keys[2][CPB];
    __shared__ unsigned long long mbar[1];
    const uint32_t mbar_a = smem_u32(&mbar[0]);

    if (tid == 0) {
        asm volatile("mbarrier.init.shared.b64 [%0], %1;"
                     :: "r"(mbar_a), "r"(CPB) : "memory");
    }
    __syncthreads();

    // ---- register-resident points + min_dist (bit-proven R7 numeric core) ----
    float px[PPT], py[PPT], pz[PPT], md[PPT];
    const int base = (int)rank * SLAB + tid;      // owned indices ascend with k
    #pragma unroll
    for (int k = 0; k < PPT; k++) {
        int i = base + k * TPB;
        px[k] = __ldg(bp + 3 * i);
        py[k] = __ldg(bp + 3 * i + 1);
        pz[k] = __ldg(bp + 3 * i + 2);
        md[k] = 1e10f;
    }

    float cx = __ldg(bp), cy = __ldg(bp + 1), cz = __ldg(bp + 2);
    if (rank == 0 && tid == 0) out[batch * NSAMP] = 0.0f;

    cluster_barrier();   // one-time: all mbarriers initialized, all CTAs resident

    for (int m = 1; m < NSAMP; m++) {
        // ---- distance update: validated d = fma(dz,dz, fma(dy,dy, dx*dx)) ----
        float vbest = -1.0f;
        #pragma unroll
        for (int k = 0; k < PPT; k++) {
            float dx = __fsub_rn(px[k], cx);
            float dy = __fsub_rn(py[k], cy);
            float dz = __fsub_rn(pz[k], cz);
            float d  = fmaf(dz, dz, fmaf(dy, dy, __fmul_rn(dx, dx)));
            float nm = fminf(md[k], d);
            md[k] = nm;
            vbest = fmaxf(vbest, nm);
        }
        // first occurrence: descending overwrite ends at SMALLEST matching k
        int bk = 0;
        #pragma unroll
        for (int k = PPT - 1; k >= 0; k--)
            if (md[k] == vbest) bk = k;
        const int bi = base + bk * TPB;

        // pack (monotone for v>=0): high=value bits, low=~idx.
        // u64 max == (value desc, idx asc) — validated comparator semantics.
        unsigned long long key =
            ((unsigned long long)__float_as_uint(vbest) << 32)
            | (unsigned int)(~(unsigned int)bi);

        // ---- warp reduce ----
        #pragma unroll
        for (int off = 16; off > 0; off >>= 1) {
            unsigned long long o = __shfl_xor_sync(0xffffffffu, key, off);
            if (o > key) key = o;
        }
        if (lane == 0) warp_keys[warp] = key;
        __syncthreads();

        // ---- block reduce (warp 0) + DSMEM key delivery + release-arrive ----
        if (warp == 0) {
            key = warp_keys[lane];
            #pragma unroll
            for (int off = 16; off > 0; off >>= 1) {
                unsigned long long o = __shfl_xor_sync(0xffffffffu, key, off);
                if (o > key) key = o;
            }
            if (lane < CPB) {
                st_remote_u64(smem_u32(&cta_keys[m & 1][rank]), (uint32_t)lane, key);
                mbar_arrive_remote(mbar_a, (uint32_t)lane);
            }
        }

        // acquire-wait: all 8 CTAs' keys for iteration m are in local smem
        mbar_wait_parity(mbar_a, (uint32_t)((m - 1) & 1));

        // ---- every thread reduces the 8 CTA keys identically ----
        unsigned long long best = cta_keys[m & 1][0];
        #pragma unroll
        for (int r = 1; r < CPB; r++) {
            unsigned long long o = cta_keys[m & 1][r];
            if (o > best) best = o;
        }
        const int widx = (int)(~(unsigned int)best);

        cx = __ldg(bp + 3 * widx);
        cy = __ldg(bp + 3 * widx + 1);
        cz = __ldg(bp + 3 * widx + 2);
        if (rank == 0 && tid == 0) out[batch * NSAMP + m] = (float)widx;
        // cta_keys slot reuse (m+2) is safe: a CTA writes m+2 only after
        // passing wait(m+1), which requires every CTA's m+1 arrival, which
        // happens only after that CTA consumed all m keys from this slot.
    }
}

extern "C" void kernel_launch(void* const* d_in, const int* in_sizes, int n_in,
                              void* d_out, int out_size) {
    const float* points = (const float*)d_in[0];
    float* out = (float*)d_out;

    cudaLaunchConfig_t cfg = {};
    cfg.gridDim  = dim3(BATCHES * CPB, 1, 1);
    cfg.blockDim = dim3(TPB, 1, 1);
    cfg.dynamicSmemBytes = 0;
    cfg.stream = 0;

    cudaLaunchAttribute attrs[1];
    attrs[0].id = cudaLaunchAttributeClusterDimension;
    attrs[0].val.clusterDim.x = CPB;
    attrs[0].val.clusterDim.y = 1;
    attrs[0].val.clusterDim.z = 1;
    cfg.attrs = attrs;
    cfg.numAttrs = 1;

    cudaLaunchKernelEx(&cfg, fps_cluster, points, out);
}